// round 12
// baseline (speedup 1.0000x reference)
#include <cuda_runtime.h>
#include <cuda_bf16.h>
#include <cstdint>
#include <math.h>

// Problem constants
#define B_    4
#define N_    4096
#define C_    1024
#define HEADS 16
#define HD    64
#define M_    (B_ * N_)        // 16384 tokens
#define GK    1024             // GEMM K dimension
#define SPLITS 8               // attention K-splits

// GEMM tiling (mma.sync m16n8k16 bf16, hi/lo split => 3 MMAs per k-step)
#define BM 128
#define BN 128
#define BK 32                  // K elements per chunk
#define KPAD 8
#define KS (BK + KPAD)         // 40 bf16 row stride in smem
#define NCHUNKS (GK / BK)      // 32
#define TILEE (BM * KS)        // bf16 elems per one array buffer (5120)
#define BUFE (4 * TILEE)       // Ah,Al,Bh,Bl per buffer (20480 elems)
#define SMEM_BYTES (2 * BUFE * 2)   // double buffer * 2B = 81920

// ---------------- scratch (device globals; no runtime allocation) ----------
__device__ __nv_bfloat16 g_xh[(size_t)M_ * C_];
__device__ __nv_bfloat16 g_xl[(size_t)M_ * C_];
__device__ __nv_bfloat16 g_wqh[(size_t)3 * C_ * C_];
__device__ __nv_bfloat16 g_wql[(size_t)3 * C_ * C_];
__device__ __nv_bfloat16 g_wph[(size_t)C_ * C_];
__device__ __nv_bfloat16 g_wpl[(size_t)C_ * C_];
__device__ __nv_bfloat16 g_hoh[(size_t)M_ * C_];
__device__ __nv_bfloat16 g_hol[(size_t)M_ * C_];
__device__ float g_qkv[(size_t)M_ * 3 * C_];          // [M, 3C] fp32
__device__ float g_part[(size_t)SPLITS * B_ * HEADS * HD * HD];
__device__ float g_attn[(size_t)B_ * HEADS * HD * HD];

// ============================ helpers ======================================
__device__ __forceinline__ void mma_bf16(float* c, const uint32_t* a, const uint32_t* b) {
    asm volatile(
        "mma.sync.aligned.m16n8k16.row.col.f32.bf16.bf16.f32 "
        "{%0,%1,%2,%3}, {%4,%5,%6,%7}, {%8,%9}, {%0,%1,%2,%3};"
        : "+f"(c[0]), "+f"(c[1]), "+f"(c[2]), "+f"(c[3])
        : "r"(a[0]), "r"(a[1]), "r"(a[2]), "r"(a[3]), "r"(b[0]), "r"(b[1]));
}
__device__ __forceinline__ void cp16(uint32_t dst, const void* src) {
    asm volatile("cp.async.cg.shared.global [%0], [%1], 16;"
                 :: "r"(dst), "l"(src) : "memory");
}
__device__ __forceinline__ uint32_t smem_u32(const void* p) {
    uint32_t a;
    asm("{ .reg .u64 t; cvta.to.shared.u64 t, %1; cvt.u32.u64 %0, t; }"
        : "=r"(a) : "l"(p));
    return a;
}
__device__ __forceinline__ void split_bf16(float v, __nv_bfloat16& hi, __nv_bfloat16& lo) {
    hi = __float2bfloat16(v);
    lo = __float2bfloat16(v - __bfloat162float(hi));
}

// ============================================================================
// bf16-split GEMM (NT): C[M_,Nn] = (Ah+Al)[M_,GK] * (Bh+Bl)[Nn,GK]^T (+bias)
// acc += Ah*Bh + Ah*Bl + Al*Bh  (fp32 accumulate, lo*lo dropped)
// grid (Nn/128, M_/128), 256 threads, 8 warps as 2(m) x 4(n), warp tile 64x32.
// ============================================================================
__global__ __launch_bounds__(256, 2) void gemm_split_kernel(
    const __nv_bfloat16* __restrict__ Ah, const __nv_bfloat16* __restrict__ Al,
    const __nv_bfloat16* __restrict__ Bh, const __nv_bfloat16* __restrict__ Bl,
    const float* __restrict__ bias, float* __restrict__ C, int Nn)
{
    extern __shared__ __nv_bfloat16 smem[];
    // buffer layout: [buf][ Ah:0 | Al:TILEE | Bh:2*TILEE | Bl:3*TILEE ]

    const int tid = threadIdx.x;
    const int wid = tid >> 5, lane = tid & 31;
    const int warp_m = wid & 1;       // 0..1
    const int warp_n = wid >> 1;      // 0..3
    const int g = lane >> 2;          // 0..7
    const int qc = lane & 3;          // 0..3

    const int row0 = blockIdx.y * BM;
    const int col0 = blockIdx.x * BN;

    // global->smem: thread loads row r = tid>>1, bf16 offset so = (tid&1)*16,
    // two 16B (8-elem) segments at so, so+8, for each of the 4 arrays.
    const int r  = tid >> 1;
    const int so = (tid & 1) * 16;
    const __nv_bfloat16* gp[4] = {
        Ah + (size_t)(row0 + r) * GK + so,
        Al + (size_t)(row0 + r) * GK + so,
        Bh + (size_t)(col0 + r) * GK + so,
        Bl + (size_t)(col0 + r) * GK + so };
    const uint32_t sbase = smem_u32(smem) + (uint32_t)(r * KS + so) * 2;

    auto issue = [&](int buf, int c) {
        const uint32_t boff = (uint32_t)buf * BUFE * 2;
        #pragma unroll
        for (int a = 0; a < 4; a++) {
            const uint32_t dst = sbase + boff + (uint32_t)a * TILEE * 2;
            const __nv_bfloat16* src = gp[a] + (size_t)c * BK;
            cp16(dst,      src);
            cp16(dst + 16, src + 8);
        }
    };

    float acc[4][4][4];
    #pragma unroll
    for (int mt = 0; mt < 4; mt++)
        #pragma unroll
        for (int nt = 0; nt < 4; nt++)
            #pragma unroll
            for (int i = 0; i < 4; i++) acc[mt][nt][i] = 0.0f;

    issue(0, 0);
    asm volatile("cp.async.commit_group;" ::: "memory");

    for (int c = 0; c < NCHUNKS; c++) {
        const int buf = c & 1;
        if (c + 1 < NCHUNKS) {
            issue(buf ^ 1, c + 1);
            asm volatile("cp.async.commit_group;" ::: "memory");
            asm volatile("cp.async.wait_group 1;" ::: "memory");
        } else {
            asm volatile("cp.async.wait_group 0;" ::: "memory");
        }
        __syncthreads();

        const __nv_bfloat16* ash = smem + (size_t)buf * BUFE;
        const __nv_bfloat16* asl = ash + TILEE;
        const __nv_bfloat16* bsh = ash + 2 * TILEE;
        const __nv_bfloat16* bsl = ash + 3 * TILEE;

        #pragma unroll
        for (int ks = 0; ks < 2; ks++) {
            const int k0 = ks * 16;
            // A fragments (hi & lo), rows g / g+8 within each 16-row tile
            uint32_t ah[4][4], al[4][4];
            #pragma unroll
            for (int mt = 0; mt < 4; mt++) {
                const int mrow = warp_m * 64 + mt * 16 + g;
                const __nv_bfloat16* ph = ash + mrow * KS + k0 + 2 * qc;
                const __nv_bfloat16* pl = asl + mrow * KS + k0 + 2 * qc;
                ah[mt][0] = *(const uint32_t*)(ph);
                ah[mt][1] = *(const uint32_t*)(ph + 8 * KS);
                ah[mt][2] = *(const uint32_t*)(ph + 8);
                ah[mt][3] = *(const uint32_t*)(ph + 8 * KS + 8);
                al[mt][0] = *(const uint32_t*)(pl);
                al[mt][1] = *(const uint32_t*)(pl + 8 * KS);
                al[mt][2] = *(const uint32_t*)(pl + 8);
                al[mt][3] = *(const uint32_t*)(pl + 8 * KS + 8);
            }
            #pragma unroll
            for (int nt = 0; nt < 4; nt++) {
                const int ncol = warp_n * 32 + nt * 8 + g;
                const __nv_bfloat16* ph = bsh + ncol * KS + k0 + 2 * qc;
                const __nv_bfloat16* pl = bsl + ncol * KS + k0 + 2 * qc;
                uint32_t bh[2], bl[2];
                bh[0] = *(const uint32_t*)(ph);
                bh[1] = *(const uint32_t*)(ph + 8);
                bl[0] = *(const uint32_t*)(pl);
                bl[1] = *(const uint32_t*)(pl + 8);
                #pragma unroll
                for (int mt = 0; mt < 4; mt++) {
                    mma_bf16(acc[mt][nt], ah[mt], bh);
                    mma_bf16(acc[mt][nt], ah[mt], bl);
                    mma_bf16(acc[mt][nt], al[mt], bh);
                }
            }
        }
        __syncthreads();
    }

    // epilogue: c0,c1 at (row g, cols 2qc,2qc+1); c2,c3 at row g+8
    #pragma unroll
    for (int mt = 0; mt < 4; mt++) {
        const int grow = row0 + warp_m * 64 + mt * 16 + g;
        #pragma unroll
        for (int nt = 0; nt < 4; nt++) {
            const int gcol = col0 + warp_n * 32 + nt * 8 + 2 * qc;
            float b0 = 0.0f, b1 = 0.0f;
            if (bias) { b0 = bias[gcol]; b1 = bias[gcol + 1]; }
            float* p0 = C + (size_t)grow * Nn + gcol;
            float* p1 = p0 + (size_t)8 * Nn;
            *(float2*)p0 = make_float2(acc[mt][nt][0] + b0, acc[mt][nt][1] + b1);
            *(float2*)p1 = make_float2(acc[mt][nt][2] + b0, acc[mt][nt][3] + b1);
        }
    }
}

// ============================================================================
// fp32 -> bf16 hi/lo split
// ============================================================================
__global__ __launch_bounds__(256) void split_kernel(
    const float4* __restrict__ s, __nv_bfloat16* __restrict__ dh,
    __nv_bfloat16* __restrict__ dl, int n4)
{
    int i = blockIdx.x * blockDim.x + threadIdx.x;
    const int stride = gridDim.x * blockDim.x;
    for (; i < n4; i += stride) {
        float4 v = s[i];
        __nv_bfloat16 h[4], l[4];
        split_bf16(v.x, h[0], l[0]);
        split_bf16(v.y, h[1], l[1]);
        split_bf16(v.z, h[2], l[2]);
        split_bf16(v.w, h[3], l[3]);
        *(uint2*)(dh + 4 * (size_t)i) = *(const uint2*)h;
        *(uint2*)(dl + 4 * (size_t)i) = *(const uint2*)l;
    }
}

// ============================================================================
// Attention logits, K-split partials: part[sp][bh][d][e] = sum_{n in split} k[n,d] q[n,e]
// ============================================================================
__global__ __launch_bounds__(256) void attn_part_kernel(
    const float* __restrict__ qkv, float* __restrict__ part)
{
    const int bh = blockIdx.x;
    const int sp = blockIdx.y;
    const int b = bh >> 4, h = bh & 15;

    __shared__ __align__(16) float Ks[64][64];
    __shared__ __align__(16) float Qs[64][64];

    const int tid = threadIdx.x;
    const int tx = tid & 15, ty = tid >> 4;
    const int lr = tid >> 2;
    const int lc = (tid & 3) * 16;

    const float* qbase = qkv + (size_t)b * N_ * (3 * C_) + h * HD;
    const float* kbase = qbase + C_;

    float acc[4][4];
    #pragma unroll
    for (int i = 0; i < 4; i++)
        #pragma unroll
        for (int j = 0; j < 4; j++) acc[i][j] = 0.0f;

    const int nbeg = sp * (N_ / SPLITS);
    const int nend = nbeg + (N_ / SPLITS);
    for (int n0 = nbeg; n0 < nend; n0 += 64) {
        const float* kp = kbase + (size_t)(n0 + lr) * (3 * C_) + lc;
        const float* qp = qbase + (size_t)(n0 + lr) * (3 * C_) + lc;
        #pragma unroll
        for (int j = 0; j < 4; j++) {
            *(float4*)&Ks[lr][lc + 4 * j] = *(const float4*)(kp + 4 * j);
            *(float4*)&Qs[lr][lc + 4 * j] = *(const float4*)(qp + 4 * j);
        }
        __syncthreads();
        #pragma unroll 8
        for (int nn = 0; nn < 64; nn++) {
            float4 kf = *(const float4*)&Ks[nn][ty * 4];
            float4 qf = *(const float4*)&Qs[nn][tx * 4];
            float ka[4] = {kf.x, kf.y, kf.z, kf.w};
            float qa[4] = {qf.x, qf.y, qf.z, qf.w};
            #pragma unroll
            for (int i = 0; i < 4; i++)
                #pragma unroll
                for (int j = 0; j < 4; j++)
                    acc[i][j] = fmaf(ka[i], qa[j], acc[i][j]);
        }
        __syncthreads();
    }

    float* op = part + (((size_t)sp * 64 + bh) * HD + ty * 4) * HD + tx * 4;
    #pragma unroll
    for (int i = 0; i < 4; i++)
        *(float4*)(op + (size_t)i * HD) =
            make_float4(acc[i][0], acc[i][1], acc[i][2], acc[i][3]);
}

// ============================================================================
// Softmax: sum partials (fixed order), scale 1/alpha, softmax over e.
// ============================================================================
__global__ __launch_bounds__(256) void softmax_kernel(
    const float* __restrict__ part, const float* __restrict__ alpha,
    float* __restrict__ attn)
{
    const int bh = blockIdx.x;
    const int h = bh & 15;
    const int tid = threadIdx.x;
    const int row = tid >> 2;
    const int seg = (tid & 3) * 16;

    float v[16];
    #pragma unroll
    for (int j = 0; j < 16; j++) v[j] = 0.0f;
    #pragma unroll
    for (int sp = 0; sp < SPLITS; sp++) {
        const float* p = part + (((size_t)sp * 64 + bh) * HD + row) * HD + seg;
        #pragma unroll
        for (int q = 0; q < 4; q++) {
            float4 t = *(const float4*)(p + 4 * q);
            v[4*q+0] += t.x; v[4*q+1] += t.y; v[4*q+2] += t.z; v[4*q+3] += t.w;
        }
    }
    const float inv_alpha = 1.0f / alpha[h];
    #pragma unroll
    for (int j = 0; j < 16; j++) v[j] *= inv_alpha;

    float m = -1e30f;
    #pragma unroll
    for (int j = 0; j < 16; j++) m = fmaxf(m, v[j]);
    m = fmaxf(m, __shfl_xor_sync(0xffffffffu, m, 1));
    m = fmaxf(m, __shfl_xor_sync(0xffffffffu, m, 2));
    float s = 0.0f;
    #pragma unroll
    for (int j = 0; j < 16; j++) { v[j] = expf(v[j] - m); s += v[j]; }
    s += __shfl_xor_sync(0xffffffffu, s, 1);
    s += __shfl_xor_sync(0xffffffffu, s, 2);
    const float invs = 1.0f / s;

    float* op = attn + ((size_t)bh * HD + row) * HD + seg;
    #pragma unroll
    for (int q = 0; q < 4; q++)
        *(float4*)(op + 4 * q) = make_float4(v[4*q]*invs, v[4*q+1]*invs,
                                             v[4*q+2]*invs, v[4*q+3]*invs);
}

// ============================================================================
// headout (hi/lo bf16 split) [b, n, h*64+d] = sum_e attn[b,h,d,e] * v[b,n,h,e]
// ============================================================================
__global__ __launch_bounds__(256) void av_kernel(
    const float* __restrict__ qkv, const float* __restrict__ attn,
    __nv_bfloat16* __restrict__ hoh, __nv_bfloat16* __restrict__ hol)
{
    const int bh = blockIdx.y;
    const int b = bh >> 4, h = bh & 15;
    const int n0 = blockIdx.x * 64;

    __shared__ __align__(16) float At[64][68];
    __shared__ __align__(16) float Vs[64][68];

    const int tid = threadIdx.x;
    const int tx = tid & 15, ty = tid >> 4;
    const int lr = tid >> 2;
    const int lc = (tid & 3) * 16;

    {
        const float* ap = attn + ((size_t)bh * HD + lr) * HD + lc;
        #pragma unroll
        for (int j = 0; j < 4; j++) {
            float4 v = *(const float4*)(ap + 4 * j);
            At[lc + 4*j + 0][lr] = v.x; At[lc + 4*j + 1][lr] = v.y;
            At[lc + 4*j + 2][lr] = v.z; At[lc + 4*j + 3][lr] = v.w;
        }
    }
    {
        const float* vp = qkv + (size_t)(b * N_ + n0 + lr) * (3 * C_) + 2 * C_ + h * HD + lc;
        #pragma unroll
        for (int j = 0; j < 4; j++)
            *(float4*)&Vs[lr][lc + 4 * j] = *(const float4*)(vp + 4 * j);
    }
    __syncthreads();

    float acc[4][4];
    #pragma unroll
    for (int i = 0; i < 4; i++)
        #pragma unroll
        for (int j = 0; j < 4; j++) acc[i][j] = 0.0f;

    #pragma unroll 8
    for (int e = 0; e < 64; e++) {
        float4 wf = *(const float4*)&At[e][tx * 4];
        float wa[4] = {wf.x, wf.y, wf.z, wf.w};
        float va[4];
        #pragma unroll
        for (int i = 0; i < 4; i++) va[i] = Vs[ty * 4 + i][e];
        #pragma unroll
        for (int i = 0; i < 4; i++)
            #pragma unroll
            for (int j = 0; j < 4; j++)
                acc[i][j] = fmaf(va[i], wa[j], acc[i][j]);
    }

    const size_t base = (size_t)(b * N_ + n0 + ty * 4) * C_ + h * HD + tx * 4;
    #pragma unroll
    for (int i = 0; i < 4; i++) {
        __nv_bfloat16 hv[4], lv[4];
        #pragma unroll
        for (int j = 0; j < 4; j++) split_bf16(acc[i][j], hv[j], lv[j]);
        *(uint2*)(hoh + base + (size_t)i * C_) = *(const uint2*)hv;
        *(uint2*)(hol + base + (size_t)i * C_) = *(const uint2*)lv;
    }
}

// ============================================================================
// launch
// inputs (metadata order): 0:x 1:H 2:W 3:Wqkv 4:Wproj 5:bproj 6:alpha
// ============================================================================
extern "C" void kernel_launch(void* const* d_in, const int* in_sizes, int n_in,
                              void* d_out, int out_size)
{
    const float* x     = (const float*)d_in[0];
    const float* Wqkv  = (const float*)d_in[3];
    const float* Wproj = (const float*)d_in[4];
    const float* bproj = (const float*)d_in[5];
    const float* alpha = (const float*)d_in[6];
    float* out = (float*)d_out;

    __nv_bfloat16 *xh, *xl, *wqh, *wql, *wph, *wpl, *hoh, *hol;
    float *qkv, *part, *attn;
    cudaGetSymbolAddress((void**)&xh,   g_xh);
    cudaGetSymbolAddress((void**)&xl,   g_xl);
    cudaGetSymbolAddress((void**)&wqh,  g_wqh);
    cudaGetSymbolAddress((void**)&wql,  g_wql);
    cudaGetSymbolAddress((void**)&wph,  g_wph);
    cudaGetSymbolAddress((void**)&wpl,  g_wpl);
    cudaGetSymbolAddress((void**)&hoh,  g_hoh);
    cudaGetSymbolAddress((void**)&hol,  g_hol);
    cudaGetSymbolAddress((void**)&qkv,  g_qkv);
    cudaGetSymbolAddress((void**)&part, g_part);
    cudaGetSymbolAddress((void**)&attn, g_attn);

    cudaFuncSetAttribute(gemm_split_kernel,
                         cudaFuncAttributeMaxDynamicSharedMemorySize, SMEM_BYTES);

    // 0) hi/lo bf16 splits
    split_kernel<<<4096, 256>>>((const float4*)x,     xh,  xl,  M_ * C_ / 4);
    split_kernel<<<1024, 256>>>((const float4*)Wqkv,  wqh, wql, 3 * C_ * C_ / 4);
    split_kernel<<<512,  256>>>((const float4*)Wproj, wph, wpl, C_ * C_ / 4);

    // 1) qkv = x * Wqkv^T  (bf16-split mma.sync)
    gemm_split_kernel<<<dim3((3 * C_) / BN, M_ / BM), 256, SMEM_BYTES>>>(
        xh, xl, wqh, wql, nullptr, qkv, 3 * C_);

    // 2) channel-attention logits (K-split) + softmax
    attn_part_kernel<<<dim3(B_ * HEADS, SPLITS), 256>>>(qkv, part);
    softmax_kernel<<<B_ * HEADS, 256>>>(part, alpha, attn);

    // 3) headout = V * attn^T, emitted as bf16 hi/lo
    av_kernel<<<dim3(N_ / 64, B_ * HEADS), 256>>>(qkv, attn, hoh, hol);

    // 4) out = headout * Wproj^T + bias (bf16-split mma.sync)
    gemm_split_kernel<<<dim3(C_ / BN, M_ / BM), 256, SMEM_BYTES>>>(
        hoh, hol, wph, wpl, bproj, out, C_);
}

// round 14
// speedup vs baseline: 1.0017x; 1.0017x over previous
#include <cuda_runtime.h>
#include <cuda_bf16.h>
#include <cstdint>
#include <math.h>

// Problem constants
#define B_    4
#define N_    4096
#define C_    1024
#define HEADS 16
#define HD    64
#define M_    (B_ * N_)        // 16384 tokens
#define GK    1024             // GEMM K dimension
#define SPLITS 8               // attention K-splits

// GEMM tiling (mma.sync m16n8k16 bf16, hi/lo split => 3 MMAs per k-step)
#define BM 128
#define BN 128
#define BK 32                  // K elements per chunk
#define KPAD 8
#define KS (BK + KPAD)         // 40 bf16 row stride in smem
#define NCHUNKS (GK / BK)      // 32
#define TILEE (BM * KS)        // bf16 elems per one array buffer (5120)
#define BUFE (4 * TILEE)       // Ah,Al,Bh,Bl per buffer (20480 elems)
#define SMEM_BYTES (2 * BUFE * 2)   // double buffer * 2B = 81920

// ---------------- scratch (device globals; no runtime allocation) ----------
__device__ __nv_bfloat16 g_xh[(size_t)M_ * C_];
__device__ __nv_bfloat16 g_xl[(size_t)M_ * C_];
__device__ __nv_bfloat16 g_wqh[(size_t)3 * C_ * C_];
__device__ __nv_bfloat16 g_wql[(size_t)3 * C_ * C_];
__device__ __nv_bfloat16 g_wph[(size_t)C_ * C_];
__device__ __nv_bfloat16 g_wpl[(size_t)C_ * C_];
__device__ __nv_bfloat16 g_hoh[(size_t)M_ * C_];
__device__ __nv_bfloat16 g_hol[(size_t)M_ * C_];
__device__ float g_qkv[(size_t)M_ * 3 * C_];          // [M, 3C] fp32
__device__ float g_part[(size_t)SPLITS * B_ * HEADS * HD * HD];
__device__ float g_attn[(size_t)B_ * HEADS * HD * HD];

// ============================ helpers ======================================
__device__ __forceinline__ void mma_bf16(float* c, const uint32_t* a, const uint32_t* b) {
    asm volatile(
        "mma.sync.aligned.m16n8k16.row.col.f32.bf16.bf16.f32 "
        "{%0,%1,%2,%3}, {%4,%5,%6,%7}, {%8,%9}, {%0,%1,%2,%3};"
        : "+f"(c[0]), "+f"(c[1]), "+f"(c[2]), "+f"(c[3])
        : "r"(a[0]), "r"(a[1]), "r"(a[2]), "r"(a[3]), "r"(b[0]), "r"(b[1]));
}
__device__ __forceinline__ void cp16(uint32_t dst, const void* src) {
    asm volatile("cp.async.cg.shared.global [%0], [%1], 16;"
                 :: "r"(dst), "l"(src) : "memory");
}
__device__ __forceinline__ uint32_t smem_u32(const void* p) {
    uint32_t a;
    asm("{ .reg .u64 t; cvta.to.shared.u64 t, %1; cvt.u32.u64 %0, t; }"
        : "=r"(a) : "l"(p));
    return a;
}
__device__ __forceinline__ void split_bf16(float v, __nv_bfloat16& hi, __nv_bfloat16& lo) {
    hi = __float2bfloat16(v);
    lo = __float2bfloat16(v - __bfloat162float(hi));
}

// ============================================================================
// bf16-split GEMM (NT): C[M_,Nn] = (Ah+Al)[M_,GK] * (Bh+Bl)[Nn,GK]^T (+bias)
// acc += Ah*Bh + Ah*Bl + Al*Bh  (fp32 accumulate, lo*lo dropped)
// grid (Nn/128, M_/128), 256 threads, 8 warps as 2(m) x 4(n), warp tile 64x32.
// ============================================================================
__global__ __launch_bounds__(256, 2) void gemm_split_kernel(
    const __nv_bfloat16* __restrict__ Ah, const __nv_bfloat16* __restrict__ Al,
    const __nv_bfloat16* __restrict__ Bh, const __nv_bfloat16* __restrict__ Bl,
    const float* __restrict__ bias, float* __restrict__ C, int Nn)
{
    extern __shared__ __nv_bfloat16 smem[];
    // buffer layout: [buf][ Ah:0 | Al:TILEE | Bh:2*TILEE | Bl:3*TILEE ]

    const int tid = threadIdx.x;
    const int wid = tid >> 5, lane = tid & 31;
    const int warp_m = wid & 1;       // 0..1
    const int warp_n = wid >> 1;      // 0..3
    const int g = lane >> 2;          // 0..7
    const int qc = lane & 3;          // 0..3

    const int row0 = blockIdx.y * BM;
    const int col0 = blockIdx.x * BN;

    // global->smem: thread loads row r = tid>>1, bf16 offset so = (tid&1)*16,
    // two 16B (8-elem) segments at so, so+8, for each of the 4 arrays.
    const int r  = tid >> 1;
    const int so = (tid & 1) * 16;
    const __nv_bfloat16* gp[4] = {
        Ah + (size_t)(row0 + r) * GK + so,
        Al + (size_t)(row0 + r) * GK + so,
        Bh + (size_t)(col0 + r) * GK + so,
        Bl + (size_t)(col0 + r) * GK + so };
    const uint32_t sbase = smem_u32(smem) + (uint32_t)(r * KS + so) * 2;

    auto issue = [&](int buf, int c) {
        const uint32_t boff = (uint32_t)buf * BUFE * 2;
        #pragma unroll
        for (int a = 0; a < 4; a++) {
            const uint32_t dst = sbase + boff + (uint32_t)a * TILEE * 2;
            const __nv_bfloat16* src = gp[a] + (size_t)c * BK;
            cp16(dst,      src);
            cp16(dst + 16, src + 8);
        }
    };

    float acc[4][4][4];
    #pragma unroll
    for (int mt = 0; mt < 4; mt++)
        #pragma unroll
        for (int nt = 0; nt < 4; nt++)
            #pragma unroll
            for (int i = 0; i < 4; i++) acc[mt][nt][i] = 0.0f;

    issue(0, 0);
    asm volatile("cp.async.commit_group;" ::: "memory");

    for (int c = 0; c < NCHUNKS; c++) {
        const int buf = c & 1;
        if (c + 1 < NCHUNKS) {
            issue(buf ^ 1, c + 1);
            asm volatile("cp.async.commit_group;" ::: "memory");
            asm volatile("cp.async.wait_group 1;" ::: "memory");
        } else {
            asm volatile("cp.async.wait_group 0;" ::: "memory");
        }
        __syncthreads();

        const __nv_bfloat16* ash = smem + (size_t)buf * BUFE;
        const __nv_bfloat16* asl = ash + TILEE;
        const __nv_bfloat16* bsh = ash + 2 * TILEE;
        const __nv_bfloat16* bsl = ash + 3 * TILEE;

        #pragma unroll
        for (int ks = 0; ks < 2; ks++) {
            const int k0 = ks * 16;
            // A fragments (hi & lo), rows g / g+8 within each 16-row tile
            uint32_t ah[4][4], al[4][4];
            #pragma unroll
            for (int mt = 0; mt < 4; mt++) {
                const int mrow = warp_m * 64 + mt * 16 + g;
                const __nv_bfloat16* ph = ash + mrow * KS + k0 + 2 * qc;
                const __nv_bfloat16* pl = asl + mrow * KS + k0 + 2 * qc;
                ah[mt][0] = *(const uint32_t*)(ph);
                ah[mt][1] = *(const uint32_t*)(ph + 8 * KS);
                ah[mt][2] = *(const uint32_t*)(ph + 8);
                ah[mt][3] = *(const uint32_t*)(ph + 8 * KS + 8);
                al[mt][0] = *(const uint32_t*)(pl);
                al[mt][1] = *(const uint32_t*)(pl + 8 * KS);
                al[mt][2] = *(const uint32_t*)(pl + 8);
                al[mt][3] = *(const uint32_t*)(pl + 8 * KS + 8);
            }
            #pragma unroll
            for (int nt = 0; nt < 4; nt++) {
                const int ncol = warp_n * 32 + nt * 8 + g;
                const __nv_bfloat16* ph = bsh + ncol * KS + k0 + 2 * qc;
                const __nv_bfloat16* pl = bsl + ncol * KS + k0 + 2 * qc;
                uint32_t bh[2], bl[2];
                bh[0] = *(const uint32_t*)(ph);
                bh[1] = *(const uint32_t*)(ph + 8);
                bl[0] = *(const uint32_t*)(pl);
                bl[1] = *(const uint32_t*)(pl + 8);
                #pragma unroll
                for (int mt = 0; mt < 4; mt++) {
                    mma_bf16(acc[mt][nt], ah[mt], bh);
                    mma_bf16(acc[mt][nt], ah[mt], bl);
                    mma_bf16(acc[mt][nt], al[mt], bh);
                }
            }
        }
        __syncthreads();
    }

    // epilogue: c0,c1 at (row g, cols 2qc,2qc+1); c2,c3 at row g+8
    #pragma unroll
    for (int mt = 0; mt < 4; mt++) {
        const int grow = row0 + warp_m * 64 + mt * 16 + g;
        #pragma unroll
        for (int nt = 0; nt < 4; nt++) {
            const int gcol = col0 + warp_n * 32 + nt * 8 + 2 * qc;
            float b0 = 0.0f, b1 = 0.0f;
            if (bias) { b0 = bias[gcol]; b1 = bias[gcol + 1]; }
            float* p0 = C + (size_t)grow * Nn + gcol;
            float* p1 = p0 + (size_t)8 * Nn;
            *(float2*)p0 = make_float2(acc[mt][nt][0] + b0, acc[mt][nt][1] + b1);
            *(float2*)p1 = make_float2(acc[mt][nt][2] + b0, acc[mt][nt][3] + b1);
        }
    }
}

// ============================================================================
// fp32 -> bf16 hi/lo split
// ============================================================================
__global__ __launch_bounds__(256) void split_kernel(
    const float4* __restrict__ s, __nv_bfloat16* __restrict__ dh,
    __nv_bfloat16* __restrict__ dl, int n4)
{
    int i = blockIdx.x * blockDim.x + threadIdx.x;
    const int stride = gridDim.x * blockDim.x;
    for (; i < n4; i += stride) {
        float4 v = s[i];
        __nv_bfloat16 h[4], l[4];
        split_bf16(v.x, h[0], l[0]);
        split_bf16(v.y, h[1], l[1]);
        split_bf16(v.z, h[2], l[2]);
        split_bf16(v.w, h[3], l[3]);
        *(uint2*)(dh + 4 * (size_t)i) = *(const uint2*)h;
        *(uint2*)(dl + 4 * (size_t)i) = *(const uint2*)l;
    }
}

// ============================================================================
// Attention logits, K-split partials: part[sp][bh][d][e] = sum_{n in split} k[n,d] q[n,e]
// ============================================================================
__global__ __launch_bounds__(256) void attn_part_kernel(
    const float* __restrict__ qkv, float* __restrict__ part)
{
    const int bh = blockIdx.x;
    const int sp = blockIdx.y;
    const int b = bh >> 4, h = bh & 15;

    __shared__ __align__(16) float Ks[64][64];
    __shared__ __align__(16) float Qs[64][64];

    const int tid = threadIdx.x;
    const int tx = tid & 15, ty = tid >> 4;
    const int lr = tid >> 2;
    const int lc = (tid & 3) * 16;

    const float* qbase = qkv + (size_t)b * N_ * (3 * C_) + h * HD;
    const float* kbase = qbase + C_;

    float acc[4][4];
    #pragma unroll
    for (int i = 0; i < 4; i++)
        #pragma unroll
        for (int j = 0; j < 4; j++) acc[i][j] = 0.0f;

    const int nbeg = sp * (N_ / SPLITS);
    const int nend = nbeg + (N_ / SPLITS);
    for (int n0 = nbeg; n0 < nend; n0 += 64) {
        const float* kp = kbase + (size_t)(n0 + lr) * (3 * C_) + lc;
        const float* qp = qbase + (size_t)(n0 + lr) * (3 * C_) + lc;
        #pragma unroll
        for (int j = 0; j < 4; j++) {
            *(float4*)&Ks[lr][lc + 4 * j] = *(const float4*)(kp + 4 * j);
            *(float4*)&Qs[lr][lc + 4 * j] = *(const float4*)(qp + 4 * j);
        }
        __syncthreads();
        #pragma unroll 8
        for (int nn = 0; nn < 64; nn++) {
            float4 kf = *(const float4*)&Ks[nn][ty * 4];
            float4 qf = *(const float4*)&Qs[nn][tx * 4];
            float ka[4] = {kf.x, kf.y, kf.z, kf.w};
            float qa[4] = {qf.x, qf.y, qf.z, qf.w};
            #pragma unroll
            for (int i = 0; i < 4; i++)
                #pragma unroll
                for (int j = 0; j < 4; j++)
                    acc[i][j] = fmaf(ka[i], qa[j], acc[i][j]);
        }
        __syncthreads();
    }

    float* op = part + (((size_t)sp * 64 + bh) * HD + ty * 4) * HD + tx * 4;
    #pragma unroll
    for (int i = 0; i < 4; i++)
        *(float4*)(op + (size_t)i * HD) =
            make_float4(acc[i][0], acc[i][1], acc[i][2], acc[i][3]);
}

// ============================================================================
// Softmax: sum partials (fixed order), scale 1/alpha, softmax over e.
// ============================================================================
__global__ __launch_bounds__(256) void softmax_kernel(
    const float* __restrict__ part, const float* __restrict__ alpha,
    float* __restrict__ attn)
{
    const int bh = blockIdx.x;
    const int h = bh & 15;
    const int tid = threadIdx.x;
    const int row = tid >> 2;
    const int seg = (tid & 3) * 16;

    float v[16];
    #pragma unroll
    for (int j = 0; j < 16; j++) v[j] = 0.0f;
    #pragma unroll
    for (int sp = 0; sp < SPLITS; sp++) {
        const float* p = part + (((size_t)sp * 64 + bh) * HD + row) * HD + seg;
        #pragma unroll
        for (int q = 0; q < 4; q++) {
            float4 t = *(const float4*)(p + 4 * q);
            v[4*q+0] += t.x; v[4*q+1] += t.y; v[4*q+2] += t.z; v[4*q+3] += t.w;
        }
    }
    const float inv_alpha = 1.0f / alpha[h];
    #pragma unroll
    for (int j = 0; j < 16; j++) v[j] *= inv_alpha;

    float m = -1e30f;
    #pragma unroll
    for (int j = 0; j < 16; j++) m = fmaxf(m, v[j]);
    m = fmaxf(m, __shfl_xor_sync(0xffffffffu, m, 1));
    m = fmaxf(m, __shfl_xor_sync(0xffffffffu, m, 2));
    float s = 0.0f;
    #pragma unroll
    for (int j = 0; j < 16; j++) { v[j] = expf(v[j] - m); s += v[j]; }
    s += __shfl_xor_sync(0xffffffffu, s, 1);
    s += __shfl_xor_sync(0xffffffffu, s, 2);
    const float invs = 1.0f / s;

    float* op = attn + ((size_t)bh * HD + row) * HD + seg;
    #pragma unroll
    for (int q = 0; q < 4; q++)
        *(float4*)(op + 4 * q) = make_float4(v[4*q]*invs, v[4*q+1]*invs,
                                             v[4*q+2]*invs, v[4*q+3]*invs);
}

// ============================================================================
// headout (hi/lo bf16 split) [b, n, h*64+d] = sum_e attn[b,h,d,e] * v[b,n,h,e]
// ============================================================================
__global__ __launch_bounds__(256) void av_kernel(
    const float* __restrict__ qkv, const float* __restrict__ attn,
    __nv_bfloat16* __restrict__ hoh, __nv_bfloat16* __restrict__ hol)
{
    const int bh = blockIdx.y;
    const int b = bh >> 4, h = bh & 15;
    const int n0 = blockIdx.x * 64;

    __shared__ __align__(16) float At[64][68];
    __shared__ __align__(16) float Vs[64][68];

    const int tid = threadIdx.x;
    const int tx = tid & 15, ty = tid >> 4;
    const int lr = tid >> 2;
    const int lc = (tid & 3) * 16;

    {
        const float* ap = attn + ((size_t)bh * HD + lr) * HD + lc;
        #pragma unroll
        for (int j = 0; j < 4; j++) {
            float4 v = *(const float4*)(ap + 4 * j);
            At[lc + 4*j + 0][lr] = v.x; At[lc + 4*j + 1][lr] = v.y;
            At[lc + 4*j + 2][lr] = v.z; At[lc + 4*j + 3][lr] = v.w;
        }
    }
    {
        const float* vp = qkv + (size_t)(b * N_ + n0 + lr) * (3 * C_) + 2 * C_ + h * HD + lc;
        #pragma unroll
        for (int j = 0; j < 4; j++)
            *(float4*)&Vs[lr][lc + 4 * j] = *(const float4*)(vp + 4 * j);
    }
    __syncthreads();

    float acc[4][4];
    #pragma unroll
    for (int i = 0; i < 4; i++)
        #pragma unroll
        for (int j = 0; j < 4; j++) acc[i][j] = 0.0f;

    #pragma unroll 8
    for (int e = 0; e < 64; e++) {
        float4 wf = *(const float4*)&At[e][tx * 4];
        float wa[4] = {wf.x, wf.y, wf.z, wf.w};
        float va[4];
        #pragma unroll
        for (int i = 0; i < 4; i++) va[i] = Vs[ty * 4 + i][e];
        #pragma unroll
        for (int i = 0; i < 4; i++)
            #pragma unroll
            for (int j = 0; j < 4; j++)
                acc[i][j] = fmaf(va[i], wa[j], acc[i][j]);
    }

    const size_t base = (size_t)(b * N_ + n0 + ty * 4) * C_ + h * HD + tx * 4;
    #pragma unroll
    for (int i = 0; i < 4; i++) {
        __nv_bfloat16 hv[4], lv[4];
        #pragma unroll
        for (int j = 0; j < 4; j++) split_bf16(acc[i][j], hv[j], lv[j]);
        *(uint2*)(hoh + base + (size_t)i * C_) = *(const uint2*)hv;
        *(uint2*)(hol + base + (size_t)i * C_) = *(const uint2*)lv;
    }
}

// ============================================================================
// launch
// inputs (metadata order): 0:x 1:H 2:W 3:Wqkv 4:Wproj 5:bproj 6:alpha
// ============================================================================
extern "C" void kernel_launch(void* const* d_in, const int* in_sizes, int n_in,
                              void* d_out, int out_size)
{
    const float* x     = (const float*)d_in[0];
    const float* Wqkv  = (const float*)d_in[3];
    const float* Wproj = (const float*)d_in[4];
    const float* bproj = (const float*)d_in[5];
    const float* alpha = (const float*)d_in[6];
    float* out = (float*)d_out;

    __nv_bfloat16 *xh, *xl, *wqh, *wql, *wph, *wpl, *hoh, *hol;
    float *qkv, *part, *attn;
    cudaGetSymbolAddress((void**)&xh,   g_xh);
    cudaGetSymbolAddress((void**)&xl,   g_xl);
    cudaGetSymbolAddress((void**)&wqh,  g_wqh);
    cudaGetSymbolAddress((void**)&wql,  g_wql);
    cudaGetSymbolAddress((void**)&wph,  g_wph);
    cudaGetSymbolAddress((void**)&wpl,  g_wpl);
    cudaGetSymbolAddress((void**)&hoh,  g_hoh);
    cudaGetSymbolAddress((void**)&hol,  g_hol);
    cudaGetSymbolAddress((void**)&qkv,  g_qkv);
    cudaGetSymbolAddress((void**)&part, g_part);
    cudaGetSymbolAddress((void**)&attn, g_attn);

    cudaFuncSetAttribute(gemm_split_kernel,
                         cudaFuncAttributeMaxDynamicSharedMemorySize, SMEM_BYTES);

    // 0) hi/lo bf16 splits
    split_kernel<<<4096, 256>>>((const float4*)x,     xh,  xl,  M_ * C_ / 4);
    split_kernel<<<1024, 256>>>((const float4*)Wqkv,  wqh, wql, 3 * C_ * C_ / 4);
    split_kernel<<<512,  256>>>((const float4*)Wproj, wph, wpl, C_ * C_ / 4);

    // 1) qkv = x * Wqkv^T  (bf16-split mma.sync)
    gemm_split_kernel<<<dim3((3 * C_) / BN, M_ / BM), 256, SMEM_BYTES>>>(
        xh, xl, wqh, wql, nullptr, qkv, 3 * C_);

    // 2) channel-attention logits (K-split) + softmax
    attn_part_kernel<<<dim3(B_ * HEADS, SPLITS), 256>>>(qkv, part);
    softmax_kernel<<<B_ * HEADS, 256>>>(part, alpha, attn);

    // 3) headout = V * attn^T, emitted as bf16 hi/lo
    av_kernel<<<dim3(N_ / 64, B_ * HEADS), 256>>>(qkv, attn, hoh, hol);

    // 4) out = headout * Wproj^T + bias (bf16-split mma.sync)
    gemm_split_kernel<<<dim3(C_ / BN, M_ / BM), 256, SMEM_BYTES>>>(
        hoh, hol, wph, wpl, bproj, out, C_);
}

// round 15
// speedup vs baseline: 1.0766x; 1.0748x over previous
#include <cuda_runtime.h>
#include <cuda_bf16.h>
#include <cstdint>
#include <math.h>

// Problem constants
#define B_    4
#define N_    4096
#define C_    1024
#define HEADS 16
#define HD    64
#define M_    (B_ * N_)        // 16384 tokens
#define GK    1024             // GEMM K dimension
#define SPLITS 8               // attention K-splits

// GEMM tiling (mma.sync m16n8k16 bf16, hi/lo split => 3 MMAs per k-step)
#define BM 128
#define BN 128
#define BK 32                  // K elements per chunk
#define KPAD 8
#define KS (BK + KPAD)         // 40 bf16 row stride in smem (conflict-free ldmatrix)
#define NCHUNKS (GK / BK)      // 32
#define TILEE (BM * KS)        // bf16 elems per one array buffer (5120)
#define BUFE (4 * TILEE)       // Ah,Al,Bh,Bl per buffer (20480 elems)
#define SMEM_BYTES (2 * BUFE * 2)   // double buffer * 2B = 81920

// ---------------- scratch (device globals; no runtime allocation) ----------
__device__ __nv_bfloat16 g_xh[(size_t)M_ * C_];
__device__ __nv_bfloat16 g_xl[(size_t)M_ * C_];
__device__ __nv_bfloat16 g_wqh[(size_t)3 * C_ * C_];
__device__ __nv_bfloat16 g_wql[(size_t)3 * C_ * C_];
__device__ __nv_bfloat16 g_wph[(size_t)C_ * C_];
__device__ __nv_bfloat16 g_wpl[(size_t)C_ * C_];
__device__ __nv_bfloat16 g_hoh[(size_t)M_ * C_];
__device__ __nv_bfloat16 g_hol[(size_t)M_ * C_];
__device__ float g_qkv[(size_t)M_ * 3 * C_];          // [M, 3C] fp32
__device__ float g_part[(size_t)SPLITS * B_ * HEADS * HD * HD];
__device__ float g_attn[(size_t)B_ * HEADS * HD * HD];

// ============================ helpers ======================================
__device__ __forceinline__ void mma_bf16(float* c, const uint32_t* a, const uint32_t* b) {
    asm volatile(
        "mma.sync.aligned.m16n8k16.row.col.f32.bf16.bf16.f32 "
        "{%0,%1,%2,%3}, {%4,%5,%6,%7}, {%8,%9}, {%0,%1,%2,%3};"
        : "+f"(c[0]), "+f"(c[1]), "+f"(c[2]), "+f"(c[3])
        : "r"(a[0]), "r"(a[1]), "r"(a[2]), "r"(a[3]), "r"(b[0]), "r"(b[1]));
}
__device__ __forceinline__ void ldm_x4(uint32_t* r, uint32_t addr) {
    asm volatile("ldmatrix.sync.aligned.m8n8.x4.shared.b16 {%0,%1,%2,%3}, [%4];"
                 : "=r"(r[0]), "=r"(r[1]), "=r"(r[2]), "=r"(r[3]) : "r"(addr));
}
__device__ __forceinline__ void cp16(uint32_t dst, const void* src) {
    asm volatile("cp.async.cg.shared.global [%0], [%1], 16;"
                 :: "r"(dst), "l"(src) : "memory");
}
__device__ __forceinline__ uint32_t smem_u32(const void* p) {
    uint32_t a;
    asm("{ .reg .u64 t; cvta.to.shared.u64 t, %1; cvt.u32.u64 %0, t; }"
        : "=r"(a) : "l"(p));
    return a;
}
__device__ __forceinline__ void split_bf16(float v, __nv_bfloat16& hi, __nv_bfloat16& lo) {
    hi = __float2bfloat16(v);
    lo = __float2bfloat16(v - __bfloat162float(hi));
}

// ============================================================================
// bf16-split GEMM (NT): C[M_,Nn] = (Ah+Al)[M_,GK] * (Bh+Bl)[Nn,GK]^T (+bias)
// acc += Ah*Bh + Ah*Bl + Al*Bh  (fp32 accumulate, lo*lo dropped)
// grid (Nn/128, M_/128), 256 threads, 8 warps as 2(m) x 4(n), warp tile 64x32.
// Fragments loaded with ldmatrix.x4; MMAs pass-ordered for latency hiding.
// ============================================================================
__global__ __launch_bounds__(256, 2) void gemm_split_kernel(
    const __nv_bfloat16* __restrict__ Ah, const __nv_bfloat16* __restrict__ Al,
    const __nv_bfloat16* __restrict__ Bh, const __nv_bfloat16* __restrict__ Bl,
    const float* __restrict__ bias, float* __restrict__ C, int Nn)
{
    extern __shared__ __nv_bfloat16 smem[];
    // buffer layout: [buf][ Ah:0 | Al:TILEE | Bh:2*TILEE | Bl:3*TILEE ]

    const int tid = threadIdx.x;
    const int wid = tid >> 5, lane = tid & 31;
    const int warp_m = wid & 1;       // 0..1
    const int warp_n = wid >> 1;      // 0..3
    const int g = lane >> 2;          // 0..7
    const int qc = lane & 3;          // 0..3

    const int row0 = blockIdx.y * BM;
    const int col0 = blockIdx.x * BN;

    // global->smem: thread loads row r = tid>>1, bf16 offset so = (tid&1)*16,
    // two 16B (8-elem) segments at so, so+8, for each of the 4 arrays.
    const int r  = tid >> 1;
    const int so = (tid & 1) * 16;
    const __nv_bfloat16* gp[4] = {
        Ah + (size_t)(row0 + r) * GK + so,
        Al + (size_t)(row0 + r) * GK + so,
        Bh + (size_t)(col0 + r) * GK + so,
        Bl + (size_t)(col0 + r) * GK + so };
    const uint32_t sm0 = smem_u32(smem);
    const uint32_t sbase = sm0 + (uint32_t)(r * KS + so) * 2;

    auto issue = [&](int buf, int c) {
        const uint32_t boff = (uint32_t)buf * BUFE * 2;
        #pragma unroll
        for (int a = 0; a < 4; a++) {
            const uint32_t dst = sbase + boff + (uint32_t)a * TILEE * 2;
            const __nv_bfloat16* src = gp[a] + (size_t)c * BK;
            cp16(dst,      src);
            cp16(dst + 16, src + 8);
        }
    };

    // ldmatrix per-lane geometry (x4):
    // A: lanes 0-7 rows 0-7 @k0 | 8-15 rows 8-15 @k0 | 16-23 rows 0-7 @k8 | 24-31 rows 8-15 @k8
    const uint32_t aoff = (uint32_t)((warp_m * 64 + (lane & 15)) * KS
                                     + ((lane >> 4) & 1) * 8) * 2;
    // B: lanes 0-7 n 0-7 @k0 | 8-15 n 0-7 @k8 | 16-23 n 8-15 @k0 | 24-31 n 8-15 @k8
    const uint32_t boff = (uint32_t)((warp_n * 32 + ((lane & 7) + ((lane & 16) >> 1))) * KS
                                     + (lane & 8)) * 2;

    float acc[4][4][4];
    #pragma unroll
    for (int mt = 0; mt < 4; mt++)
        #pragma unroll
        for (int nt = 0; nt < 4; nt++)
            #pragma unroll
            for (int i = 0; i < 4; i++) acc[mt][nt][i] = 0.0f;

    issue(0, 0);
    asm volatile("cp.async.commit_group;" ::: "memory");

    for (int c = 0; c < NCHUNKS; c++) {
        const int buf = c & 1;
        if (c + 1 < NCHUNKS) {
            issue(buf ^ 1, c + 1);
            asm volatile("cp.async.commit_group;" ::: "memory");
            asm volatile("cp.async.wait_group 1;" ::: "memory");
        } else {
            asm volatile("cp.async.wait_group 0;" ::: "memory");
        }
        __syncthreads();

        const uint32_t base   = sm0 + (uint32_t)buf * BUFE * 2;
        const uint32_t ahb = base + aoff;
        const uint32_t alb = ahb + TILEE * 2;
        const uint32_t bhb = base + 2 * TILEE * 2 + boff;
        const uint32_t blb = bhb + TILEE * 2;

        #pragma unroll
        for (int ks = 0; ks < 2; ks++) {
            const uint32_t koff = (uint32_t)ks * 16 * 2;

            // B fragments: bhr[nt*2 .. nt*2+1] is the frag for column tile nt
            uint32_t bhr[8], blr[8];
            ldm_x4(&bhr[0], bhb + koff);
            ldm_x4(&bhr[4], bhb + koff + 16 * KS * 2);
            ldm_x4(&blr[0], blb + koff);
            ldm_x4(&blr[4], blb + koff + 16 * KS * 2);

            #pragma unroll
            for (int mtp = 0; mtp < 2; mtp++) {
                uint32_t ahr[8], alr[8];
                ldm_x4(&ahr[0], ahb + koff + (uint32_t)(mtp * 32)      * KS * 2);
                ldm_x4(&ahr[4], ahb + koff + (uint32_t)(mtp * 32 + 16) * KS * 2);
                ldm_x4(&alr[0], alb + koff + (uint32_t)(mtp * 32)      * KS * 2);
                ldm_x4(&alr[4], alb + koff + (uint32_t)(mtp * 32 + 16) * KS * 2);

                // pass 1: hi*hi  (8 independent MMAs)
                #pragma unroll
                for (int m = 0; m < 2; m++)
                    #pragma unroll
                    for (int nt = 0; nt < 4; nt++)
                        mma_bf16(acc[mtp * 2 + m][nt], &ahr[m * 4], &bhr[nt * 2]);
                // pass 2: hi*lo
                #pragma unroll
                for (int m = 0; m < 2; m++)
                    #pragma unroll
                    for (int nt = 0; nt < 4; nt++)
                        mma_bf16(acc[mtp * 2 + m][nt], &ahr[m * 4], &blr[nt * 2]);
                // pass 3: lo*hi
                #pragma unroll
                for (int m = 0; m < 2; m++)
                    #pragma unroll
                    for (int nt = 0; nt < 4; nt++)
                        mma_bf16(acc[mtp * 2 + m][nt], &alr[m * 4], &bhr[nt * 2]);
            }
        }
        __syncthreads();
    }

    // epilogue: c0,c1 at (row g, cols 2qc,2qc+1); c2,c3 at row g+8
    #pragma unroll
    for (int mt = 0; mt < 4; mt++) {
        const int grow = row0 + warp_m * 64 + mt * 16 + g;
        #pragma unroll
        for (int nt = 0; nt < 4; nt++) {
            const int gcol = col0 + warp_n * 32 + nt * 8 + 2 * qc;
            float b0 = 0.0f, b1 = 0.0f;
            if (bias) { b0 = bias[gcol]; b1 = bias[gcol + 1]; }
            float* p0 = C + (size_t)grow * Nn + gcol;
            float* p1 = p0 + (size_t)8 * Nn;
            *(float2*)p0 = make_float2(acc[mt][nt][0] + b0, acc[mt][nt][1] + b1);
            *(float2*)p1 = make_float2(acc[mt][nt][2] + b0, acc[mt][nt][3] + b1);
        }
    }
}

// ============================================================================
// fp32 -> bf16 hi/lo split
// ============================================================================
__global__ __launch_bounds__(256) void split_kernel(
    const float4* __restrict__ s, __nv_bfloat16* __restrict__ dh,
    __nv_bfloat16* __restrict__ dl, int n4)
{
    int i = blockIdx.x * blockDim.x + threadIdx.x;
    const int stride = gridDim.x * blockDim.x;
    for (; i < n4; i += stride) {
        float4 v = s[i];
        __nv_bfloat16 h[4], l[4];
        split_bf16(v.x, h[0], l[0]);
        split_bf16(v.y, h[1], l[1]);
        split_bf16(v.z, h[2], l[2]);
        split_bf16(v.w, h[3], l[3]);
        *(uint2*)(dh + 4 * (size_t)i) = *(const uint2*)h;
        *(uint2*)(dl + 4 * (size_t)i) = *(const uint2*)l;
    }
}

// ============================================================================
// Attention logits, K-split partials: part[sp][bh][d][e] = sum_{n in split} k[n,d] q[n,e]
// ============================================================================
__global__ __launch_bounds__(256) void attn_part_kernel(
    const float* __restrict__ qkv, float* __restrict__ part)
{
    const int bh = blockIdx.x;
    const int sp = blockIdx.y;
    const int b = bh >> 4, h = bh & 15;

    __shared__ __align__(16) float Ks[64][64];
    __shared__ __align__(16) float Qs[64][64];

    const int tid = threadIdx.x;
    const int tx = tid & 15, ty = tid >> 4;
    const int lr = tid >> 2;
    const int lc = (tid & 3) * 16;

    const float* qbase = qkv + (size_t)b * N_ * (3 * C_) + h * HD;
    const float* kbase = qbase + C_;

    float acc[4][4];
    #pragma unroll
    for (int i = 0; i < 4; i++)
        #pragma unroll
        for (int j = 0; j < 4; j++) acc[i][j] = 0.0f;

    const int nbeg = sp * (N_ / SPLITS);
    const int nend = nbeg + (N_ / SPLITS);
    for (int n0 = nbeg; n0 < nend; n0 += 64) {
        const float* kp = kbase + (size_t)(n0 + lr) * (3 * C_) + lc;
        const float* qp = qbase + (size_t)(n0 + lr) * (3 * C_) + lc;
        #pragma unroll
        for (int j = 0; j < 4; j++) {
            *(float4*)&Ks[lr][lc + 4 * j] = *(const float4*)(kp + 4 * j);
            *(float4*)&Qs[lr][lc + 4 * j] = *(const float4*)(qp + 4 * j);
        }
        __syncthreads();
        #pragma unroll 8
        for (int nn = 0; nn < 64; nn++) {
            float4 kf = *(const float4*)&Ks[nn][ty * 4];
            float4 qf = *(const float4*)&Qs[nn][tx * 4];
            float ka[4] = {kf.x, kf.y, kf.z, kf.w};
            float qa[4] = {qf.x, qf.y, qf.z, qf.w};
            #pragma unroll
            for (int i = 0; i < 4; i++)
                #pragma unroll
                for (int j = 0; j < 4; j++)
                    acc[i][j] = fmaf(ka[i], qa[j], acc[i][j]);
        }
        __syncthreads();
    }

    float* op = part + (((size_t)sp * 64 + bh) * HD + ty * 4) * HD + tx * 4;
    #pragma unroll
    for (int i = 0; i < 4; i++)
        *(float4*)(op + (size_t)i * HD) =
            make_float4(acc[i][0], acc[i][1], acc[i][2], acc[i][3]);
}

// ============================================================================
// Softmax: sum partials (fixed order), scale 1/alpha, softmax over e.
// ============================================================================
__global__ __launch_bounds__(256) void softmax_kernel(
    const float* __restrict__ part, const float* __restrict__ alpha,
    float* __restrict__ attn)
{
    const int bh = blockIdx.x;
    const int h = bh & 15;
    const int tid = threadIdx.x;
    const int row = tid >> 2;
    const int seg = (tid & 3) * 16;

    float v[16];
    #pragma unroll
    for (int j = 0; j < 16; j++) v[j] = 0.0f;
    #pragma unroll
    for (int sp = 0; sp < SPLITS; sp++) {
        const float* p = part + (((size_t)sp * 64 + bh) * HD + row) * HD + seg;
        #pragma unroll
        for (int q = 0; q < 4; q++) {
            float4 t = *(const float4*)(p + 4 * q);
            v[4*q+0] += t.x; v[4*q+1] += t.y; v[4*q+2] += t.z; v[4*q+3] += t.w;
        }
    }
    const float inv_alpha = 1.0f / alpha[h];
    #pragma unroll
    for (int j = 0; j < 16; j++) v[j] *= inv_alpha;

    float m = -1e30f;
    #pragma unroll
    for (int j = 0; j < 16; j++) m = fmaxf(m, v[j]);
    m = fmaxf(m, __shfl_xor_sync(0xffffffffu, m, 1));
    m = fmaxf(m, __shfl_xor_sync(0xffffffffu, m, 2));
    float s = 0.0f;
    #pragma unroll
    for (int j = 0; j < 16; j++) { v[j] = expf(v[j] - m); s += v[j]; }
    s += __shfl_xor_sync(0xffffffffu, s, 1);
    s += __shfl_xor_sync(0xffffffffu, s, 2);
    const float invs = 1.0f / s;

    float* op = attn + ((size_t)bh * HD + row) * HD + seg;
    #pragma unroll
    for (int q = 0; q < 4; q++)
        *(float4*)(op + 4 * q) = make_float4(v[4*q]*invs, v[4*q+1]*invs,
                                             v[4*q+2]*invs, v[4*q+3]*invs);
}

// ============================================================================
// headout (hi/lo bf16 split) [b, n, h*64+d] = sum_e attn[b,h,d,e] * v[b,n,h,e]
// ============================================================================
__global__ __launch_bounds__(256) void av_kernel(
    const float* __restrict__ qkv, const float* __restrict__ attn,
    __nv_bfloat16* __restrict__ hoh, __nv_bfloat16* __restrict__ hol)
{
    const int bh = blockIdx.y;
    const int b = bh >> 4, h = bh & 15;
    const int n0 = blockIdx.x * 64;

    __shared__ __align__(16) float At[64][68];
    __shared__ __align__(16) float Vs[64][68];

    const int tid = threadIdx.x;
    const int tx = tid & 15, ty = tid >> 4;
    const int lr = tid >> 2;
    const int lc = (tid & 3) * 16;

    {
        const float* ap = attn + ((size_t)bh * HD + lr) * HD + lc;
        #pragma unroll
        for (int j = 0; j < 4; j++) {
            float4 v = *(const float4*)(ap + 4 * j);
            At[lc + 4*j + 0][lr] = v.x; At[lc + 4*j + 1][lr] = v.y;
            At[lc + 4*j + 2][lr] = v.z; At[lc + 4*j + 3][lr] = v.w;
        }
    }
    {
        const float* vp = qkv + (size_t)(b * N_ + n0 + lr) * (3 * C_) + 2 * C_ + h * HD + lc;
        #pragma unroll
        for (int j = 0; j < 4; j++)
            *(float4*)&Vs[lr][lc + 4 * j] = *(const float4*)(vp + 4 * j);
    }
    __syncthreads();

    float acc[4][4];
    #pragma unroll
    for (int i = 0; i < 4; i++)
        #pragma unroll
        for (int j = 0; j < 4; j++) acc[i][j] = 0.0f;

    #pragma unroll 8
    for (int e = 0; e < 64; e++) {
        float4 wf = *(const float4*)&At[e][tx * 4];
        float wa[4] = {wf.x, wf.y, wf.z, wf.w};
        float va[4];
        #pragma unroll
        for (int i = 0; i < 4; i++) va[i] = Vs[ty * 4 + i][e];
        #pragma unroll
        for (int i = 0; i < 4; i++)
            #pragma unroll
            for (int j = 0; j < 4; j++)
                acc[i][j] = fmaf(va[i], wa[j], acc[i][j]);
    }

    const size_t base = (size_t)(b * N_ + n0 + ty * 4) * C_ + h * HD + tx * 4;
    #pragma unroll
    for (int i = 0; i < 4; i++) {
        __nv_bfloat16 hv[4], lv[4];
        #pragma unroll
        for (int j = 0; j < 4; j++) split_bf16(acc[i][j], hv[j], lv[j]);
        *(uint2*)(hoh + base + (size_t)i * C_) = *(const uint2*)hv;
        *(uint2*)(hol + base + (size_t)i * C_) = *(const uint2*)lv;
    }
}

// ============================================================================
// launch
// inputs (metadata order): 0:x 1:H 2:W 3:Wqkv 4:Wproj 5:bproj 6:alpha
// ============================================================================
extern "C" void kernel_launch(void* const* d_in, const int* in_sizes, int n_in,
                              void* d_out, int out_size)
{
    const float* x     = (const float*)d_in[0];
    const float* Wqkv  = (const float*)d_in[3];
    const float* Wproj = (const float*)d_in[4];
    const float* bproj = (const float*)d_in[5];
    const float* alpha = (const float*)d_in[6];
    float* out = (float*)d_out;

    __nv_bfloat16 *xh, *xl, *wqh, *wql, *wph, *wpl, *hoh, *hol;
    float *qkv, *part, *attn;
    cudaGetSymbolAddress((void**)&xh,   g_xh);
    cudaGetSymbolAddress((void**)&xl,   g_xl);
    cudaGetSymbolAddress((void**)&wqh,  g_wqh);
    cudaGetSymbolAddress((void**)&wql,  g_wql);
    cudaGetSymbolAddress((void**)&wph,  g_wph);
    cudaGetSymbolAddress((void**)&wpl,  g_wpl);
    cudaGetSymbolAddress((void**)&hoh,  g_hoh);
    cudaGetSymbolAddress((void**)&hol,  g_hol);
    cudaGetSymbolAddress((void**)&qkv,  g_qkv);
    cudaGetSymbolAddress((void**)&part, g_part);
    cudaGetSymbolAddress((void**)&attn, g_attn);

    cudaFuncSetAttribute(gemm_split_kernel,
                         cudaFuncAttributeMaxDynamicSharedMemorySize, SMEM_BYTES);

    // 0) hi/lo bf16 splits
    split_kernel<<<4096, 256>>>((const float4*)x,     xh,  xl,  M_ * C_ / 4);
    split_kernel<<<1024, 256>>>((const float4*)Wqkv,  wqh, wql, 3 * C_ * C_ / 4);
    split_kernel<<<512,  256>>>((const float4*)Wproj, wph, wpl, C_ * C_ / 4);

    // 1) qkv = x * Wqkv^T  (bf16-split mma.sync)
    gemm_split_kernel<<<dim3((3 * C_) / BN, M_ / BM), 256, SMEM_BYTES>>>(
        xh, xl, wqh, wql, nullptr, qkv, 3 * C_);

    // 2) channel-attention logits (K-split) + softmax
    attn_part_kernel<<<dim3(B_ * HEADS, SPLITS), 256>>>(qkv, part);
    softmax_kernel<<<B_ * HEADS, 256>>>(part, alpha, attn);

    // 3) headout = V * attn^T, emitted as bf16 hi/lo
    av_kernel<<<dim3(N_ / 64, B_ * HEADS), 256>>>(qkv, attn, hoh, hol);

    // 4) out = headout * Wproj^T + bias (bf16-split mma.sync)
    gemm_split_kernel<<<dim3(C_ / BN, M_ / BM), 256, SMEM_BYTES>>>(
        hoh, hol, wph, wpl, bproj, out, C_);
}